// round 1
// baseline (speedup 1.0000x reference)
#include <cuda_runtime.h>
#include <math.h>

#define D   256
#define NA  16
#define NC  256

// ---------------------------------------------------------------------------
// Scratch (device globals — no allocation allowed in kernel_launch)
// ---------------------------------------------------------------------------
__device__ float g_qads[8192u  * 256u];
__device__ float g_kads[8192u  * 256u];
__device__ float g_vads[8192u  * 256u];
__device__ float g_qcat[131072u * 256u];
__device__ float g_kcat[131072u * 256u];
__device__ float g_vcat[131072u * 256u];

// ---------------------------------------------------------------------------
// Packed fp32 (FFMA2) helpers — B300 fp32 FFMA is half-rate; f32x2 restores it
// ---------------------------------------------------------------------------
__device__ __forceinline__ unsigned long long pk2(float lo, float hi) {
    unsigned long long r;
    asm("mov.b64 %0, {%1, %2};" : "=l"(r) : "f"(lo), "f"(hi));
    return r;
}
__device__ __forceinline__ void fma2(unsigned long long& d,
                                     unsigned long long a,
                                     unsigned long long b) {
    asm("fma.rn.f32x2 %0, %1, %2, %0;" : "+l"(d) : "l"(a), "l"(b));
}
__device__ __forceinline__ float2 upk2(unsigned long long v) {
    float2 r;
    asm("mov.b64 {%0, %1}, %2;" : "=f"(r.x), "=f"(r.y) : "l"(v));
    return r;
}

// ---------------------------------------------------------------------------
// GEMM: Y[M,256] = X[M,256] @ W[256,256]^T + bias   (row dot row, "NT")
// BM=BN=128, BK=16, 256 threads, 8x8 micro-tile per thread (split 4+4 halves)
// ---------------------------------------------------------------------------
__global__ void __launch_bounds__(256, 2)
gemm_nt_bias(const float* __restrict__ X, const float* __restrict__ W,
             const float* __restrict__ bias, float* __restrict__ Y)
{
    __shared__ __align__(16) float Xs[16][132];
    __shared__ __align__(16) float Ws[16][132];

    const int tid = threadIdx.x;
    const int r0  = blockIdx.x * 128;
    const int n0  = blockIdx.y * 128;
    const int tm  = tid >> 4;    // 0..15
    const int tn  = tid & 15;    // 0..15

    unsigned long long acc[8][4];
#pragma unroll
    for (int i = 0; i < 8; i++)
#pragma unroll
        for (int j = 0; j < 4; j++) acc[i][j] = 0ull;

    const float4* X4 = (const float4*)X;
    const float4* W4 = (const float4*)W;

    for (int k0 = 0; k0 < 256; k0 += 16) {
        __syncthreads();
        // load 128x16 tiles (transposed into smem: Xs[k][m], Ws[k][n])
#pragma unroll
        for (int h2 = 0; h2 < 2; h2++) {
            int i   = tid + h2 * 256;     // 0..511 float4s
            int row = i >> 2;             // 0..127
            int kq  = i & 3;              // 0..3
            float4 xv = X4[(size_t)(r0 + row) * 64 + (k0 >> 2) + kq];
            Xs[kq*4+0][row] = xv.x;
            Xs[kq*4+1][row] = xv.y;
            Xs[kq*4+2][row] = xv.z;
            Xs[kq*4+3][row] = xv.w;
            float4 wv = W4[(size_t)(n0 + row) * 64 + (k0 >> 2) + kq];
            Ws[kq*4+0][row] = wv.x;
            Ws[kq*4+1][row] = wv.y;
            Ws[kq*4+2][row] = wv.z;
            Ws[kq*4+3][row] = wv.w;
        }
        __syncthreads();
#pragma unroll
        for (int k = 0; k < 16; k++) {
            float4 a0 = *(const float4*)&Xs[k][tm*4];
            float4 a1 = *(const float4*)&Xs[k][64 + tm*4];
            float4 b0 = *(const float4*)&Ws[k][tn*4];
            float4 b1 = *(const float4*)&Ws[k][64 + tn*4];
            unsigned long long bp[4];
            bp[0] = pk2(b0.x, b0.y); bp[1] = pk2(b0.z, b0.w);
            bp[2] = pk2(b1.x, b1.y); bp[3] = pk2(b1.z, b1.w);
            float av[8] = {a0.x, a0.y, a0.z, a0.w, a1.x, a1.y, a1.z, a1.w};
#pragma unroll
            for (int i = 0; i < 8; i++) {
                unsigned long long ad = pk2(av[i], av[i]);
#pragma unroll
                for (int jp = 0; jp < 4; jp++) fma2(acc[i][jp], ad, bp[jp]);
            }
        }
    }

    float4 bv0 = *(const float4*)(bias + n0 + tn*4);
    float4 bv1 = *(const float4*)(bias + n0 + 64 + tn*4);
#pragma unroll
    for (int i = 0; i < 8; i++) {
        int m = r0 + ((i < 4) ? (tm*4 + i) : (64 + tm*4 + i - 4));
        float2 p0 = upk2(acc[i][0]);
        float2 p1 = upk2(acc[i][1]);
        float2 p2 = upk2(acc[i][2]);
        float2 p3 = upk2(acc[i][3]);
        float4 o0 = make_float4(p0.x + bv0.x, p0.y + bv0.y, p1.x + bv0.z, p1.y + bv0.w);
        float4 o1 = make_float4(p2.x + bv1.x, p2.y + bv1.y, p3.x + bv1.z, p3.y + bv1.w);
        *(float4*)(Y + (size_t)m * 256 + n0 + tn*4)      = o0;
        *(float4*)(Y + (size_t)m * 256 + n0 + 64 + tn*4) = o1;
    }
}

// ---------------------------------------------------------------------------
// Ads attention: per graph b, S = Q_ads(16xD) K_cat(256xD)^T, softmax over 256
// keys, U = P V_cat, then out = l2norm(h_ads + U). Block per graph.
// Dynamic smem: Qs[16][260] | Ps[16][260] | KVs[32][260]  (66,560 B)
// ---------------------------------------------------------------------------
__global__ void __launch_bounds__(256)
attn_ads_kernel(const float* __restrict__ q, const float* __restrict__ k,
                const float* __restrict__ v, const float* __restrict__ h,
                float* __restrict__ out)
{
    extern __shared__ __align__(16) float sm[];
    float* Qs  = sm;              // 16 x 260
    float* Ps  = sm + 16 * 260;   // 16 x 260
    float* KVs = sm + 32 * 260;   // 32 x 260

    const int b   = blockIdx.x;
    const int tid = threadIdx.x;
    const float scale = 0.0625f;   // 1/sqrt(256)

    // load Q (16 x 256)
    {
        const float4* src = (const float4*)(q + (size_t)b * (NA * D));
#pragma unroll
        for (int h2 = 0; h2 < 4; h2++) {
            int i = tid + h2 * 256;
            int row = i >> 6;
            int col = (i & 63) << 2;
            float4 vv = src[i];
            float* d = Qs + row * 260 + col;
            d[0] = vv.x; d[1] = vv.y; d[2] = vv.z; d[3] = vv.w;
        }
    }
    __syncthreads();

    const int a  = tid >> 4;   // 0..15 query row
    const int cl = tid & 15;   // key sub-index

    // pass 1: scores
    for (int c0 = 0; c0 < 256; c0 += 32) {
        const float4* src = (const float4*)(k + ((size_t)b * NC + c0) * D);
#pragma unroll
        for (int h2 = 0; h2 < 8; h2++) {
            int i = tid + h2 * 256;
            int row = i >> 6;
            int col = (i & 63) << 2;
            float4 vv = src[i];
            float* d = KVs + row * 260 + col;
            d[0] = vv.x; d[1] = vv.y; d[2] = vv.z; d[3] = vv.w;
        }
        __syncthreads();
        float s0 = 0.f, s1 = 0.f;
        const float* qa  = Qs  + a * 260;
        const float* k0p = KVs + cl * 260;
        const float* k1p = KVs + (16 + cl) * 260;
#pragma unroll 8
        for (int d4 = 0; d4 < 256; d4 += 4) {
            float4 qv  = *(const float4*)(qa  + d4);
            float4 k0v = *(const float4*)(k0p + d4);
            float4 k1v = *(const float4*)(k1p + d4);
            s0 += qv.x*k0v.x + qv.y*k0v.y + qv.z*k0v.z + qv.w*k0v.w;
            s1 += qv.x*k1v.x + qv.y*k1v.y + qv.z*k1v.z + qv.w*k1v.w;
        }
        Ps[a * 260 + c0 + cl]      = s0 * scale;
        Ps[a * 260 + c0 + 16 + cl] = s1 * scale;
        __syncthreads();
    }

    // softmax (warp per row)
    {
        const int warp = tid >> 5, lane = tid & 31;
        for (int r = warp; r < 16; r += 8) {
            float* row = Ps + r * 260;
            float vals[8];
            float mx = -1e30f;
#pragma unroll
            for (int j = 0; j < 8; j++) { vals[j] = row[lane + 32*j]; mx = fmaxf(mx, vals[j]); }
#pragma unroll
            for (int o = 16; o > 0; o >>= 1) mx = fmaxf(mx, __shfl_xor_sync(0xffffffffu, mx, o));
            float sum = 0.f;
#pragma unroll
            for (int j = 0; j < 8; j++) { vals[j] = expf(vals[j] - mx); sum += vals[j]; }
#pragma unroll
            for (int o = 16; o > 0; o >>= 1) sum += __shfl_xor_sync(0xffffffffu, sum, o);
            float inv = 1.f / sum;
#pragma unroll
            for (int j = 0; j < 8; j++) row[lane + 32*j] = vals[j] * inv;
        }
    }
    __syncthreads();

    // pass 2: U = P V ; thread owns (a, dims dbase..dbase+15)
    const int dbase = (tid & 15) * 16;
    float4 u0 = make_float4(0,0,0,0), u1 = u0, u2 = u0, u3 = u0;
    for (int c0 = 0; c0 < 256; c0 += 32) {
        const float4* src = (const float4*)(v + ((size_t)b * NC + c0) * D);
#pragma unroll
        for (int h2 = 0; h2 < 8; h2++) {
            int i = tid + h2 * 256;
            int row = i >> 6;
            int col = (i & 63) << 2;
            float4 vv = src[i];
            float* d = KVs + row * 260 + col;
            d[0] = vv.x; d[1] = vv.y; d[2] = vv.z; d[3] = vv.w;
        }
        __syncthreads();
#pragma unroll 4
        for (int c = 0; c < 32; c++) {
            float p = Ps[a * 260 + c0 + c];
            const float4* vr = (const float4*)(KVs + c * 260 + dbase);
            float4 v0 = vr[0], v1 = vr[1], v2 = vr[2], v3 = vr[3];
            u0.x += p*v0.x; u0.y += p*v0.y; u0.z += p*v0.z; u0.w += p*v0.w;
            u1.x += p*v1.x; u1.y += p*v1.y; u1.z += p*v1.z; u1.w += p*v1.w;
            u2.x += p*v2.x; u2.y += p*v2.y; u2.z += p*v2.z; u2.w += p*v2.w;
            u3.x += p*v3.x; u3.y += p*v3.y; u3.z += p*v3.z; u3.w += p*v3.w;
        }
        __syncthreads();
    }

    // residual + l2 norm
    const size_t row = (size_t)(b * NA + a) * D + dbase;
    const float4* hr = (const float4*)(h + row);
    float4 r0 = hr[0], r1 = hr[1], r2 = hr[2], r3 = hr[3];
    r0.x += u0.x; r0.y += u0.y; r0.z += u0.z; r0.w += u0.w;
    r1.x += u1.x; r1.y += u1.y; r1.z += u1.z; r1.w += u1.w;
    r2.x += u2.x; r2.y += u2.y; r2.z += u2.z; r2.w += u2.w;
    r3.x += u3.x; r3.y += u3.y; r3.z += u3.z; r3.w += u3.w;
    float ss = r0.x*r0.x + r0.y*r0.y + r0.z*r0.z + r0.w*r0.w
             + r1.x*r1.x + r1.y*r1.y + r1.z*r1.z + r1.w*r1.w
             + r2.x*r2.x + r2.y*r2.y + r2.z*r2.z + r2.w*r2.w
             + r3.x*r3.x + r3.y*r3.y + r3.z*r3.z + r3.w*r3.w;
    Qs[a * 16 + (tid & 15)] = ss;
    __syncthreads();
    float tot = 0.f;
#pragma unroll
    for (int j = 0; j < 16; j++) tot += Qs[a * 16 + j];
    float inv = 1.f / fmaxf(sqrtf(tot), 1e-12f);
    float4* o = (float4*)(out + row);
    o[0] = make_float4(r0.x*inv, r0.y*inv, r0.z*inv, r0.w*inv);
    o[1] = make_float4(r1.x*inv, r1.y*inv, r1.z*inv, r1.w*inv);
    o[2] = make_float4(r2.x*inv, r2.y*inv, r2.z*inv, r2.w*inv);
    o[3] = make_float4(r3.x*inv, r3.y*inv, r3.z*inv, r3.w*inv);
}

// ---------------------------------------------------------------------------
// Cat attention: per graph b, each query row c (of 256): softmax over 16
// ads keys, U = P V_ads, out = l2norm(h_cat + U). Warp per query.
// grid = (8, B), block = 256 threads (8 warps x 4 queries each)
// ---------------------------------------------------------------------------
__global__ void __launch_bounds__(256)
attn_cat_kernel(const float* __restrict__ q, const float* __restrict__ k,
                const float* __restrict__ v, const float* __restrict__ h,
                float* __restrict__ out)
{
    __shared__ __align__(16) float Ks[16][264];
    __shared__ __align__(16) float Vs[16][264];

    const int b   = blockIdx.y;
    const int tid = threadIdx.x;
    const float scale = 0.0625f;

    {
        const float4* ks = (const float4*)(k + (size_t)b * (NA * D));
        const float4* vs = (const float4*)(v + (size_t)b * (NA * D));
#pragma unroll
        for (int h2 = 0; h2 < 4; h2++) {
            int i = tid + h2 * 256;
            int row = i >> 6;
            int col = (i & 63) << 2;
            float4 kv = ks[i];
            Ks[row][col] = kv.x; Ks[row][col+1] = kv.y; Ks[row][col+2] = kv.z; Ks[row][col+3] = kv.w;
            float4 vv = vs[i];
            Vs[row][col] = vv.x; Vs[row][col+1] = vv.y; Vs[row][col+2] = vv.z; Vs[row][col+3] = vv.w;
        }
    }
    __syncthreads();

    const int warp = tid >> 5, lane = tid & 31;
#pragma unroll 1
    for (int qi = 0; qi < 4; qi++) {
        const int c = blockIdx.x * 32 + warp * 4 + qi;
        const size_t gr = (size_t)b * NC + c;
        const float4* qr = (const float4*)(q + gr * D);
        float4 qa = qr[lane], qb = qr[32 + lane];   // dims 4l..4l+3, 128+4l..

        float s[16];
#pragma unroll
        for (int a2 = 0; a2 < 16; a2++) {
            const float4* kr = (const float4*)&Ks[a2][0];
            float4 ka = kr[lane], kb = kr[32 + lane];
            float p = qa.x*ka.x + qa.y*ka.y + qa.z*ka.z + qa.w*ka.w
                    + qb.x*kb.x + qb.y*kb.y + qb.z*kb.z + qb.w*kb.w;
#pragma unroll
            for (int o = 16; o > 0; o >>= 1) p += __shfl_xor_sync(0xffffffffu, p, o);
            s[a2] = p * scale;
        }
        float mx = s[0];
#pragma unroll
        for (int a2 = 1; a2 < 16; a2++) mx = fmaxf(mx, s[a2]);
        float sum = 0.f;
#pragma unroll
        for (int a2 = 0; a2 < 16; a2++) { s[a2] = expf(s[a2] - mx); sum += s[a2]; }
        float pinv = 1.f / sum;

        float4 ua = make_float4(0,0,0,0), ub = ua;
#pragma unroll
        for (int a2 = 0; a2 < 16; a2++) {
            float p = s[a2] * pinv;
            const float4* vr = (const float4*)&Vs[a2][0];
            float4 va = vr[lane], vb = vr[32 + lane];
            ua.x += p*va.x; ua.y += p*va.y; ua.z += p*va.z; ua.w += p*va.w;
            ub.x += p*vb.x; ub.y += p*vb.y; ub.z += p*vb.z; ub.w += p*vb.w;
        }
        const float4* hr = (const float4*)(h + gr * D);
        float4 ra = hr[lane], rb = hr[32 + lane];
        ra.x += ua.x; ra.y += ua.y; ra.z += ua.z; ra.w += ua.w;
        rb.x += ub.x; rb.y += ub.y; rb.z += ub.z; rb.w += ub.w;
        float nn = ra.x*ra.x + ra.y*ra.y + ra.z*ra.z + ra.w*ra.w
                 + rb.x*rb.x + rb.y*rb.y + rb.z*rb.z + rb.w*rb.w;
#pragma unroll
        for (int o = 16; o > 0; o >>= 1) nn += __shfl_xor_sync(0xffffffffu, nn, o);
        float inv2 = 1.f / fmaxf(sqrtf(nn), 1e-12f);
        float4* o4 = (float4*)(out + gr * D);
        o4[lane]      = make_float4(ra.x*inv2, ra.y*inv2, ra.z*inv2, ra.w*inv2);
        o4[32 + lane] = make_float4(rb.x*inv2, rb.y*inv2, rb.z*inv2, rb.w*inv2);
    }
}

// ---------------------------------------------------------------------------
// Launch
// ---------------------------------------------------------------------------
extern "C" void kernel_launch(void* const* d_in, const int* in_sizes, int n_in,
                              void* d_out, int out_size)
{
    const float* h_ads = (const float*)d_in[0];
    const float* h_cat = (const float*)d_in[1];
    const float* Wq_a = (const float*)d_in[2];  const float* bq_a = (const float*)d_in[3];
    const float* Wk_a = (const float*)d_in[4];  const float* bk_a = (const float*)d_in[5];
    const float* Wv_a = (const float*)d_in[6];  const float* bv_a = (const float*)d_in[7];
    const float* Wq_c = (const float*)d_in[8];  const float* bq_c = (const float*)d_in[9];
    const float* Wk_c = (const float*)d_in[10]; const float* bk_c = (const float*)d_in[11];
    const float* Wv_c = (const float*)d_in[12]; const float* bv_c = (const float*)d_in[13];

    const int M_ads = in_sizes[0] / D;   // 8192
    const int M_cat = in_sizes[1] / D;   // 131072
    const int B     = M_ads / NA;        // 512

    float *qa, *ka, *va, *qc, *kc, *vc;
    cudaGetSymbolAddress((void**)&qa, g_qads);
    cudaGetSymbolAddress((void**)&ka, g_kads);
    cudaGetSymbolAddress((void**)&va, g_vads);
    cudaGetSymbolAddress((void**)&qc, g_qcat);
    cudaGetSymbolAddress((void**)&kc, g_kcat);
    cudaGetSymbolAddress((void**)&vc, g_vcat);

    dim3 thr(256);

    gemm_nt_bias<<<dim3(M_ads / 128, 2), thr>>>(h_ads, Wq_a, bq_a, qa);
    gemm_nt_bias<<<dim3(M_ads / 128, 2), thr>>>(h_ads, Wk_a, bk_a, ka);
    gemm_nt_bias<<<dim3(M_ads / 128, 2), thr>>>(h_ads, Wv_a, bv_a, va);
    gemm_nt_bias<<<dim3(M_cat / 128, 2), thr>>>(h_cat, Wq_c, bq_c, qc);
    gemm_nt_bias<<<dim3(M_cat / 128, 2), thr>>>(h_cat, Wk_c, bk_c, kc);
    gemm_nt_bias<<<dim3(M_cat / 128, 2), thr>>>(h_cat, Wv_c, bv_c, vc);

    const int ads_smem = 64 * 260 * 4;  // 66,560 B
    cudaFuncSetAttribute((const void*)attn_ads_kernel,
                         cudaFuncAttributeMaxDynamicSharedMemorySize, ads_smem);

    attn_ads_kernel<<<B, thr, ads_smem>>>(qa, kc, vc, h_ads, (float*)d_out);
    attn_cat_kernel<<<dim3(8, B), thr>>>(qc, ka, va, h_cat,
                                         (float*)d_out + (size_t)M_ads * D);
}

// round 3
// speedup vs baseline: 1.1724x; 1.1724x over previous
#include <cuda_runtime.h>
#include <cuda_bf16.h>
#include <math.h>
#include <stdint.h>

#define D   256
#define NA  16
#define NC  256
#define LDT 72   // smem bf16 row stride (64 + 8 pad -> conflict-free ldmatrix)

// ---------------------------------------------------------------------------
// Scratch (device globals — no allocation allowed in kernel_launch)
// ---------------------------------------------------------------------------
__device__ float g_qads[8192u  * 256u];
__device__ float g_kads[8192u  * 256u];
__device__ float g_vads[8192u  * 256u];
__device__ float g_qcat[131072u * 256u];
__device__ float g_kcat[131072u * 256u];
__device__ float g_vcat[131072u * 256u];

// ---------------------------------------------------------------------------
// PTX helpers (arch-neutral: sm_80+ — NO tcgen05, harness targets plain sm_103)
// ---------------------------------------------------------------------------
__device__ __forceinline__ uint32_t smem_u32(const void* p) {
    uint32_t a;
    asm("{ .reg .u64 t; cvta.to.shared.u64 t, %1; cvt.u32.u64 %0, t; }"
        : "=r"(a) : "l"(p));
    return a;
}
__device__ __forceinline__ void sts128(uint32_t a, uint32_t x, uint32_t y,
                                       uint32_t z, uint32_t w) {
    asm volatile("st.shared.v4.b32 [%0], {%1,%2,%3,%4};"
                 :: "r"(a), "r"(x), "r"(y), "r"(z), "r"(w) : "memory");
}
__device__ __forceinline__ void ldm_x4(uint32_t* r, uint32_t addr) {
    asm volatile("ldmatrix.sync.aligned.m8n8.x4.shared.b16 {%0,%1,%2,%3}, [%4];"
                 : "=r"(r[0]), "=r"(r[1]), "=r"(r[2]), "=r"(r[3]) : "r"(addr));
}
__device__ __forceinline__ void mma16816(float* c, const uint32_t* a,
                                         const uint32_t* b) {
    asm volatile(
        "mma.sync.aligned.m16n8k16.row.col.f32.bf16.bf16.f32 "
        "{%0,%1,%2,%3}, {%4,%5,%6,%7}, {%8,%9}, {%0,%1,%2,%3};"
        : "+f"(c[0]), "+f"(c[1]), "+f"(c[2]), "+f"(c[3])
        : "r"(a[0]), "r"(a[1]), "r"(a[2]), "r"(a[3]), "r"(b[0]), "r"(b[1]));
}
// split a,b (fp32) into packed bf16 hi pair + bf16 lo pair (lo = x - bf16(x))
__device__ __forceinline__ void split2(float a, float b, uint32_t& hp, uint32_t& lp) {
    asm("cvt.rn.bf16x2.f32 %0, %1, %2;" : "=r"(hp) : "f"(b), "f"(a));
    float af = __uint_as_float(hp << 16);
    float bf = __uint_as_float(hp & 0xFFFF0000u);
    float la = a - af, lb = b - bf;
    asm("cvt.rn.bf16x2.f32 %0, %1, %2;" : "=r"(lp) : "f"(lb), "f"(la));
}

// ---------------------------------------------------------------------------
// Tensor-core GEMM via mma.sync: Y[M,256] = X[M,256] @ W[256,256]^T + bias
// bf16 3-way split (hi*hi + lo*hi + hi*lo), fp32 accumulate in registers.
// CTA 256 thr = 8 warps (4m x 2n), tile 128x128, K in 4 chunks of 64.
// ---------------------------------------------------------------------------
__global__ void __launch_bounds__(256)
gemm_mma(const float* __restrict__ X, const float* __restrict__ W,
         const float* __restrict__ bias, float* __restrict__ Y)
{
    extern __shared__ __align__(16) __nv_bfloat16 smb[];
    const uint32_t sAh = smem_u32(smb);
    const uint32_t sAl = sAh + 128 * LDT * 2;
    const uint32_t sBh = sAl + 128 * LDT * 2;
    const uint32_t sBl = sBh + 128 * LDT * 2;

    const int tid  = threadIdx.x;
    const int lane = tid & 31;
    const int wid  = tid >> 5;
    const int wm   = wid & 3;
    const int wn   = wid >> 2;
    const int m0   = blockIdx.x * 128;
    const int n0   = blockIdx.y * 128;

    float acc[2][8][4];
#pragma unroll
    for (int i = 0; i < 2; i++)
#pragma unroll
        for (int j = 0; j < 8; j++)
#pragma unroll
            for (int t = 0; t < 4; t++) acc[i][j][t] = 0.f;

    const int lrow = tid >> 1;            // 0..127
    const int lcol = (tid & 1) * 32;      // 0 or 32

    // ldmatrix per-lane address parts
    const uint32_t a_rowoff = (uint32_t)((wm * 32 + (lane & 15)) * LDT) * 2;
    const uint32_t b_rowoff = (uint32_t)((wn * 64 + (lane & 15)) * LDT) * 2;
    const uint32_t AM_STEP  = 16 * LDT * 2;   // +16 rows

    for (int k0 = 0; k0 < 256; k0 += 64) {
        if (k0) __syncthreads();

        // ---- load + split A chunk (128 x 64 fp32) ----
        {
            const float4* src = (const float4*)(X + (size_t)(m0 + lrow) * 256 + k0 + lcol);
            uint32_t dh = sAh + (uint32_t)(lrow * LDT + lcol) * 2;
            uint32_t dl = sAl + (uint32_t)(lrow * LDT + lcol) * 2;
#pragma unroll
            for (int j = 0; j < 4; j++) {
                float4 f0 = src[2 * j], f1 = src[2 * j + 1];
                uint32_t h0, h1, h2, h3, l0, l1, l2, l3;
                split2(f0.x, f0.y, h0, l0); split2(f0.z, f0.w, h1, l1);
                split2(f1.x, f1.y, h2, l2); split2(f1.z, f1.w, h3, l3);
                sts128(dh + j * 16, h0, h1, h2, h3);
                sts128(dl + j * 16, l0, l1, l2, l3);
            }
        }
        // ---- load + split B chunk (W rows n0..n0+127) ----
        {
            const float4* src = (const float4*)(W + (size_t)(n0 + lrow) * 256 + k0 + lcol);
            uint32_t dh = sBh + (uint32_t)(lrow * LDT + lcol) * 2;
            uint32_t dl = sBl + (uint32_t)(lrow * LDT + lcol) * 2;
#pragma unroll
            for (int j = 0; j < 4; j++) {
                float4 f0 = src[2 * j], f1 = src[2 * j + 1];
                uint32_t h0, h1, h2, h3, l0, l1, l2, l3;
                split2(f0.x, f0.y, h0, l0); split2(f0.z, f0.w, h1, l1);
                split2(f1.x, f1.y, h2, l2); split2(f1.z, f1.w, h3, l3);
                sts128(dh + j * 16, h0, h1, h2, h3);
                sts128(dl + j * 16, l0, l1, l2, l3);
            }
        }
        __syncthreads();

#pragma unroll
        for (int ks = 0; ks < 4; ks++) {
            const uint32_t colp = (uint32_t)(ks * 16 + (lane >> 4) * 8) * 2;
            const uint32_t aoff = a_rowoff + colp;
            const uint32_t boff = b_rowoff + colp;

            uint32_t a[2][4];
            uint32_t b[8][2];

            // pass 0: Ahi * Bhi
            ldm_x4(a[0], sAh + aoff);
            ldm_x4(a[1], sAh + aoff + AM_STEP);
#pragma unroll
            for (int bp = 0; bp < 4; bp++) {
                uint32_t r[4];
                ldm_x4(r, sBh + boff + bp * AM_STEP);
                b[2*bp][0] = r[0]; b[2*bp+1][0] = r[1];
                b[2*bp][1] = r[2]; b[2*bp+1][1] = r[3];
            }
#pragma unroll
            for (int am = 0; am < 2; am++)
#pragma unroll
                for (int bn = 0; bn < 8; bn++) mma16816(acc[am][bn], a[am], b[bn]);

            // pass 1: Alo * Bhi (reuse B)
            ldm_x4(a[0], sAl + aoff);
            ldm_x4(a[1], sAl + aoff + AM_STEP);
#pragma unroll
            for (int am = 0; am < 2; am++)
#pragma unroll
                for (int bn = 0; bn < 8; bn++) mma16816(acc[am][bn], a[am], b[bn]);

            // pass 2: Ahi * Blo
            ldm_x4(a[0], sAh + aoff);
            ldm_x4(a[1], sAh + aoff + AM_STEP);
#pragma unroll
            for (int bp = 0; bp < 4; bp++) {
                uint32_t r[4];
                ldm_x4(r, sBl + boff + bp * AM_STEP);
                b[2*bp][0] = r[0]; b[2*bp+1][0] = r[1];
                b[2*bp][1] = r[2]; b[2*bp+1][1] = r[3];
            }
#pragma unroll
            for (int am = 0; am < 2; am++)
#pragma unroll
                for (int bn = 0; bn < 8; bn++) mma16816(acc[am][bn], a[am], b[bn]);
        }
    }

    // ---- epilogue: add bias, store fp32 ----
    const int orow  = m0 + wm * 32 + (lane >> 2);
    const int ocol0 = n0 + wn * 64 + (lane & 3) * 2;
#pragma unroll
    for (int am = 0; am < 2; am++) {
#pragma unroll
        for (int bn = 0; bn < 8; bn++) {
            const int col = ocol0 + bn * 8;
            float2 bv = *(const float2*)(bias + col);
            float2 v0, v1;
            v0.x = acc[am][bn][0] + bv.x; v0.y = acc[am][bn][1] + bv.y;
            v1.x = acc[am][bn][2] + bv.x; v1.y = acc[am][bn][3] + bv.y;
            *(float2*)(Y + (size_t)(orow + am * 16)     * 256 + col) = v0;
            *(float2*)(Y + (size_t)(orow + am * 16 + 8) * 256 + col) = v1;
        }
    }
}

// ---------------------------------------------------------------------------
// Ads attention: per graph b, S = Q_ads(16xD) K_cat(256xD)^T, softmax over 256
// keys, U = P V_cat, then out = l2norm(h_ads + U). Block per graph.
// ---------------------------------------------------------------------------
__global__ void __launch_bounds__(256)
attn_ads_kernel(const float* __restrict__ q, const float* __restrict__ k,
                const float* __restrict__ v, const float* __restrict__ h,
                float* __restrict__ out)
{
    extern __shared__ __align__(16) float sm[];
    float* Qs  = sm;              // 16 x 260
    float* Ps  = sm + 16 * 260;   // 16 x 260
    float* KVs = sm + 32 * 260;   // 32 x 260

    const int b   = blockIdx.x;
    const int tid = threadIdx.x;
    const float scale = 0.0625f;   // 1/sqrt(256)

    {
        const float4* src = (const float4*)(q + (size_t)b * (NA * D));
#pragma unroll
        for (int h2 = 0; h2 < 4; h2++) {
            int i = tid + h2 * 256;
            int row = i >> 6;
            int col = (i & 63) << 2;
            float4 vv = src[i];
            float* d = Qs + row * 260 + col;
            d[0] = vv.x; d[1] = vv.y; d[2] = vv.z; d[3] = vv.w;
        }
    }
    __syncthreads();

    const int a  = tid >> 4;
    const int cl = tid & 15;

    for (int c0 = 0; c0 < 256; c0 += 32) {
        const float4* src = (const float4*)(k + ((size_t)b * NC + c0) * D);
#pragma unroll
        for (int h2 = 0; h2 < 8; h2++) {
            int i = tid + h2 * 256;
            int row = i >> 6;
            int col = (i & 63) << 2;
            float4 vv = src[i];
            float* d = KVs + row * 260 + col;
            d[0] = vv.x; d[1] = vv.y; d[2] = vv.z; d[3] = vv.w;
        }
        __syncthreads();
        float s0 = 0.f, s1 = 0.f;
        const float* qa  = Qs  + a * 260;
        const float* k0p = KVs + cl * 260;
        const float* k1p = KVs + (16 + cl) * 260;
#pragma unroll 8
        for (int d4 = 0; d4 < 256; d4 += 4) {
            float4 qv  = *(const float4*)(qa  + d4);
            float4 k0v = *(const float4*)(k0p + d4);
            float4 k1v = *(const float4*)(k1p + d4);
            s0 += qv.x*k0v.x + qv.y*k0v.y + qv.z*k0v.z + qv.w*k0v.w;
            s1 += qv.x*k1v.x + qv.y*k1v.y + qv.z*k1v.z + qv.w*k1v.w;
        }
        Ps[a * 260 + c0 + cl]      = s0 * scale;
        Ps[a * 260 + c0 + 16 + cl] = s1 * scale;
        __syncthreads();
    }

    {
        const int warp = tid >> 5, lane = tid & 31;
        for (int r = warp; r < 16; r += 8) {
            float* row = Ps + r * 260;
            float vals[8];
            float mx = -1e30f;
#pragma unroll
            for (int j = 0; j < 8; j++) { vals[j] = row[lane + 32*j]; mx = fmaxf(mx, vals[j]); }
#pragma unroll
            for (int o = 16; o > 0; o >>= 1) mx = fmaxf(mx, __shfl_xor_sync(0xffffffffu, mx, o));
            float sum = 0.f;
#pragma unroll
            for (int j = 0; j < 8; j++) { vals[j] = expf(vals[j] - mx); sum += vals[j]; }
#pragma unroll
            for (int o = 16; o > 0; o >>= 1) sum += __shfl_xor_sync(0xffffffffu, sum, o);
            float inv = 1.f / sum;
#pragma unroll
            for (int j = 0; j < 8; j++) row[lane + 32*j] = vals[j] * inv;
        }
    }
    __syncthreads();

    const int dbase = (tid & 15) * 16;
    float4 u0 = make_float4(0,0,0,0), u1 = u0, u2 = u0, u3 = u0;
    for (int c0 = 0; c0 < 256; c0 += 32) {
        const float4* src = (const float4*)(v + ((size_t)b * NC + c0) * D);
#pragma unroll
        for (int h2 = 0; h2 < 8; h2++) {
            int i = tid + h2 * 256;
            int row = i >> 6;
            int col = (i & 63) << 2;
            float4 vv = src[i];
            float* d = KVs + row * 260 + col;
            d[0] = vv.x; d[1] = vv.y; d[2] = vv.z; d[3] = vv.w;
        }
        __syncthreads();
#pragma unroll 4
        for (int c = 0; c < 32; c++) {
            float p = Ps[a * 260 + c0 + c];
            const float4* vr = (const float4*)(KVs + c * 260 + dbase);
            float4 v0 = vr[0], v1 = vr[1], v2 = vr[2], v3 = vr[3];
            u0.x += p*v0.x; u0.y += p*v0.y; u0.z += p*v0.z; u0.w += p*v0.w;
            u1.x += p*v1.x; u1.y += p*v1.y; u1.z += p*v1.z; u1.w += p*v1.w;
            u2.x += p*v2.x; u2.y += p*v2.y; u2.z += p*v2.z; u2.w += p*v2.w;
            u3.x += p*v3.x; u3.y += p*v3.y; u3.z += p*v3.z; u3.w += p*v3.w;
        }
        __syncthreads();
    }

    const size_t row = (size_t)(b * NA + a) * D + dbase;
    const float4* hr = (const float4*)(h + row);
    float4 r0 = hr[0], r1 = hr[1], r2 = hr[2], r3 = hr[3];
    r0.x += u0.x; r0.y += u0.y; r0.z += u0.z; r0.w += u0.w;
    r1.x += u1.x; r1.y += u1.y; r1.z += u1.z; r1.w += u1.w;
    r2.x += u2.x; r2.y += u2.y; r2.z += u2.z; r2.w += u2.w;
    r3.x += u3.x; r3.y += u3.y; r3.z += u3.z; r3.w += u3.w;
    float ss = r0.x*r0.x + r0.y*r0.y + r0.z*r0.z + r0.w*r0.w
             + r1.x*r1.x + r1.y*r1.y + r1.z*r1.z + r1.w*r1.w
             + r2.x*r2.x + r2.y*r2.y + r2.z*r2.z + r2.w*r2.w
             + r3.x*r3.x + r3.y*r3.y + r3.z*r3.z + r3.w*r3.w;
    Qs[a * 16 + (tid & 15)] = ss;
    __syncthreads();
    float tot = 0.f;
#pragma unroll
    for (int j = 0; j < 16; j++) tot += Qs[a * 16 + j];
    float inv = 1.f / fmaxf(sqrtf(tot), 1e-12f);
    float4* o = (float4*)(out + row);
    o[0] = make_float4(r0.x*inv, r0.y*inv, r0.z*inv, r0.w*inv);
    o[1] = make_float4(r1.x*inv, r1.y*inv, r1.z*inv, r1.w*inv);
    o[2] = make_float4(r2.x*inv, r2.y*inv, r2.z*inv, r2.w*inv);
    o[3] = make_float4(r3.x*inv, r3.y*inv, r3.z*inv, r3.w*inv);
}

// ---------------------------------------------------------------------------
// Cat attention: warp per query. grid = (8, B), block = 256
// ---------------------------------------------------------------------------
__global__ void __launch_bounds__(256)
attn_cat_kernel(const float* __restrict__ q, const float* __restrict__ k,
                const float* __restrict__ v, const float* __restrict__ h,
                float* __restrict__ out)
{
    __shared__ __align__(16) float Ks[16][264];
    __shared__ __align__(16) float Vs[16][264];

    const int b   = blockIdx.y;
    const int tid = threadIdx.x;
    const float scale = 0.0625f;

    {
        const float4* ks = (const float4*)(k + (size_t)b * (NA * D));
        const float4* vs = (const float4*)(v + (size_t)b * (NA * D));
#pragma unroll
        for (int h2 = 0; h2 < 4; h2++) {
            int i = tid + h2 * 256;
            int row = i >> 6;
            int col = (i & 63) << 2;
            float4 kv = ks[i];
            Ks[row][col] = kv.x; Ks[row][col+1] = kv.y; Ks[row][col+2] = kv.z; Ks[row][col+3] = kv.w;
            float4 vv = vs[i];
            Vs[row][col] = vv.x; Vs[row][col+1] = vv.y; Vs[row][col+2] = vv.z; Vs[row][col+3] = vv.w;
        }
    }
    __syncthreads();

    const int warp = tid >> 5, lane = tid & 31;
#pragma unroll 1
    for (int qi = 0; qi < 4; qi++) {
        const int c = blockIdx.x * 32 + warp * 4 + qi;
        const size_t gr = (size_t)b * NC + c;
        const float4* qr = (const float4*)(q + gr * D);
        float4 qa = qr[lane], qb = qr[32 + lane];

        float s[16];
#pragma unroll
        for (int a2 = 0; a2 < 16; a2++) {
            const float4* kr = (const float4*)&Ks[a2][0];
            float4 ka = kr[lane], kb = kr[32 + lane];
            float p = qa.x*ka.x + qa.y*ka.y + qa.z*ka.z + qa.w*ka.w
                    + qb.x*kb.x + qb.y*kb.y + qb.z*kb.z + qb.w*kb.w;
#pragma unroll
            for (int o = 16; o > 0; o >>= 1) p += __shfl_xor_sync(0xffffffffu, p, o);
            s[a2] = p * scale;
        }
        float mx = s[0];
#pragma unroll
        for (int a2 = 1; a2 < 16; a2++) mx = fmaxf(mx, s[a2]);
        float sum = 0.f;
#pragma unroll
        for (int a2 = 0; a2 < 16; a2++) { s[a2] = expf(s[a2] - mx); sum += s[a2]; }
        float pinv = 1.f / sum;

        float4 ua = make_float4(0,0,0,0), ub = ua;
#pragma unroll
        for (int a2 = 0; a2 < 16; a2++) {
            float p = s[a2] * pinv;
            const float4* vr = (const float4*)&Vs[a2][0];
            float4 va = vr[lane], vb = vr[32 + lane];
            ua.x += p*va.x; ua.y += p*va.y; ua.z += p*va.z; ua.w += p*va.w;
            ub.x += p*vb.x; ub.y += p*vb.y; ub.z += p*vb.z; ub.w += p*vb.w;
        }
        const float4* hr = (const float4*)(h + gr * D);
        float4 ra = hr[lane], rb = hr[32 + lane];
        ra.x += ua.x; ra.y += ua.y; ra.z += ua.z; ra.w += ua.w;
        rb.x += ub.x; rb.y += ub.y; rb.z += ub.z; rb.w += ub.w;
        float nn = ra.x*ra.x + ra.y*ra.y + ra.z*ra.z + ra.w*ra.w
                 + rb.x*rb.x + rb.y*rb.y + rb.z*rb.z + rb.w*rb.w;
#pragma unroll
        for (int o = 16; o > 0; o >>= 1) nn += __shfl_xor_sync(0xffffffffu, nn, o);
        float inv2 = 1.f / fmaxf(sqrtf(nn), 1e-12f);
        float4* o4 = (float4*)(out + gr * D);
        o4[lane]      = make_float4(ra.x*inv2, ra.y*inv2, ra.z*inv2, ra.w*inv2);
        o4[32 + lane] = make_float4(rb.x*inv2, rb.y*inv2, rb.z*inv2, rb.w*inv2);
    }
}

// ---------------------------------------------------------------------------
// Launch
// ---------------------------------------------------------------------------
extern "C" void kernel_launch(void* const* d_in, const int* in_sizes, int n_in,
                              void* d_out, int out_size)
{
    const float* h_ads = (const float*)d_in[0];
    const float* h_cat = (const float*)d_in[1];
    const float* Wq_a = (const float*)d_in[2];  const float* bq_a = (const float*)d_in[3];
    const float* Wk_a = (const float*)d_in[4];  const float* bk_a = (const float*)d_in[5];
    const float* Wv_a = (const float*)d_in[6];  const float* bv_a = (const float*)d_in[7];
    const float* Wq_c = (const float*)d_in[8];  const float* bq_c = (const float*)d_in[9];
    const float* Wk_c = (const float*)d_in[10]; const float* bk_c = (const float*)d_in[11];
    const float* Wv_c = (const float*)d_in[12]; const float* bv_c = (const float*)d_in[13];

    const int M_ads = in_sizes[0] / D;   // 8192
    const int M_cat = in_sizes[1] / D;   // 131072
    const int B     = M_ads / NA;        // 512

    float *qa, *ka, *va, *qc, *kc, *vc;
    cudaGetSymbolAddress((void**)&qa, g_qads);
    cudaGetSymbolAddress((void**)&ka, g_kads);
    cudaGetSymbolAddress((void**)&va, g_vads);
    cudaGetSymbolAddress((void**)&qc, g_qcat);
    cudaGetSymbolAddress((void**)&kc, g_kcat);
    cudaGetSymbolAddress((void**)&vc, g_vcat);

    const int gemm_smem = 4 * 128 * LDT * 2;   // 73,728 B
    cudaFuncSetAttribute((const void*)gemm_mma,
                         cudaFuncAttributeMaxDynamicSharedMemorySize, gemm_smem);

    gemm_mma<<<dim3(M_ads / 128, 2), 256, gemm_smem>>>(h_ads, Wq_a, bq_a, qa);
    gemm_mma<<<dim3(M_ads / 128, 2), 256, gemm_smem>>>(h_ads, Wk_a, bk_a, ka);
    gemm_mma<<<dim3(M_ads / 128, 2), 256, gemm_smem>>>(h_ads, Wv_a, bv_a, va);
    gemm_mma<<<dim3(M_cat / 128, 2), 256, gemm_smem>>>(h_cat, Wq_c, bq_c, qc);
    gemm_mma<<<dim3(M_cat / 128, 2), 256, gemm_smem>>>(h_cat, Wk_c, bk_c, kc);
    gemm_mma<<<dim3(M_cat / 128, 2), 256, gemm_smem>>>(h_cat, Wv_c, bv_c, vc);

    const int ads_smem = 64 * 260 * 4;
    cudaFuncSetAttribute((const void*)attn_ads_kernel,
                         cudaFuncAttributeMaxDynamicSharedMemorySize, ads_smem);

    attn_ads_kernel<<<B, 256, ads_smem>>>(qa, kc, vc, h_ads, (float*)d_out);
    attn_cat_kernel<<<dim3(8, B), 256>>>(qc, ka, va, h_cat,
                                         (float*)d_out + (size_t)M_ads * D);
}

// round 4
// speedup vs baseline: 1.1844x; 1.0102x over previous
#include <cuda_runtime.h>
#include <cuda_bf16.h>
#include <math.h>
#include <stdint.h>

#define D   256
#define NA  16
#define NC  256
#define LDT 72   // smem bf16 row stride (64 + 8 pad -> conflict-free ldmatrix)

// ---------------------------------------------------------------------------
// Scratch (device globals — no allocation allowed in kernel_launch)
// ---------------------------------------------------------------------------
__device__ float g_qads[8192u  * 256u];
__device__ float g_kads[8192u  * 256u];
__device__ float g_vads[8192u  * 256u];
__device__ float g_qcat[131072u * 256u];
__device__ float g_kcat[131072u * 256u];
__device__ float g_vcat[131072u * 256u];

// ---------------------------------------------------------------------------
// PTX helpers (arch-neutral sm_80+ — harness ptxas target is plain sm_103)
// ---------------------------------------------------------------------------
__device__ __forceinline__ uint32_t smem_u32(const void* p) {
    uint32_t a;
    asm("{ .reg .u64 t; cvta.to.shared.u64 t, %1; cvt.u32.u64 %0, t; }"
        : "=r"(a) : "l"(p));
    return a;
}
__device__ __forceinline__ void sts128(uint32_t a, uint32_t x, uint32_t y,
                                       uint32_t z, uint32_t w) {
    asm volatile("st.shared.v4.b32 [%0], {%1,%2,%3,%4};"
                 :: "r"(a), "r"(x), "r"(y), "r"(z), "r"(w) : "memory");
}
__device__ __forceinline__ void ldm_x4(uint32_t* r, uint32_t addr) {
    asm volatile("ldmatrix.sync.aligned.m8n8.x4.shared.b16 {%0,%1,%2,%3}, [%4];"
                 : "=r"(r[0]), "=r"(r[1]), "=r"(r[2]), "=r"(r[3]) : "r"(addr));
}
__device__ __forceinline__ void mma16816(float* c, const uint32_t* a,
                                         const uint32_t* b) {
    asm volatile(
        "mma.sync.aligned.m16n8k16.row.col.f32.bf16.bf16.f32 "
        "{%0,%1,%2,%3}, {%4,%5,%6,%7}, {%8,%9}, {%0,%1,%2,%3};"
        : "+f"(c[0]), "+f"(c[1]), "+f"(c[2]), "+f"(c[3])
        : "r"(a[0]), "r"(a[1]), "r"(a[2]), "r"(a[3]), "r"(b[0]), "r"(b[1]));
}
__device__ __forceinline__ void split2(float a, float b, uint32_t& hp, uint32_t& lp) {
    asm("cvt.rn.bf16x2.f32 %0, %1, %2;" : "=r"(hp) : "f"(b), "f"(a));
    float af = __uint_as_float(hp << 16);
    float bf = __uint_as_float(hp & 0xFFFF0000u);
    float la = a - af, lb = b - bf;
    asm("cvt.rn.bf16x2.f32 %0, %1, %2;" : "=r"(lp) : "f"(lb), "f"(la));
}

// ---------------------------------------------------------------------------
// Tensor-core GEMM: Y[M,256] = X[M,256] @ W[256,256]^T + bias  (3 W via grid z)
// bf16 3-way split, 128 thr / 4 warps of 64x64, tile 128x128, BK=64.
// ---------------------------------------------------------------------------
__global__ void __launch_bounds__(128, 2)
gemm_mma3(const float* __restrict__ X,
          const float* __restrict__ W0, const float* __restrict__ W1,
          const float* __restrict__ W2,
          const float* __restrict__ b0, const float* __restrict__ b1,
          const float* __restrict__ b2,
          float* __restrict__ Y0, float* __restrict__ Y1, float* __restrict__ Y2)
{
    const int z = blockIdx.z;
    const float* W    = (z == 0) ? W0 : (z == 1) ? W1 : W2;
    const float* bias = (z == 0) ? b0 : (z == 1) ? b1 : b2;
    float*       Y    = (z == 0) ? Y0 : (z == 1) ? Y1 : Y2;

    extern __shared__ __align__(16) __nv_bfloat16 smb[];
    const uint32_t sAh = smem_u32(smb);
    const uint32_t sAl = sAh + 128 * LDT * 2;
    const uint32_t sBh = sAl + 128 * LDT * 2;
    const uint32_t sBl = sBh + 128 * LDT * 2;

    const int tid  = threadIdx.x;
    const int lane = tid & 31;
    const int wid  = tid >> 5;
    const int wm   = wid & 1;
    const int wn   = wid >> 1;
    const int m0   = blockIdx.x * 128;
    const int n0   = blockIdx.y * 128;

    float acc[4][8][4];
#pragma unroll
    for (int i = 0; i < 4; i++)
#pragma unroll
        for (int j = 0; j < 8; j++)
#pragma unroll
            for (int t = 0; t < 4; t++) acc[i][j][t] = 0.f;

    const uint32_t a_rowoff = (uint32_t)((wm * 64 + (lane & 15)) * LDT) * 2;
    const uint32_t b_rowoff = (uint32_t)((wn * 64 + (lane & 15)) * LDT) * 2;
    const uint32_t AM_STEP  = 16 * LDT * 2;

    for (int k0 = 0; k0 < 256; k0 += 64) {
        if (k0) __syncthreads();
        // A rows m0+tid, B rows n0+tid — 64 cols each, split to hi/lo
        {
            const float4* srcA = (const float4*)(X + (size_t)(m0 + tid) * 256 + k0);
            const float4* srcB = (const float4*)(W + (size_t)(n0 + tid) * 256 + k0);
            const uint32_t dA = (uint32_t)(tid * LDT) * 2;
#pragma unroll
            for (int j = 0; j < 8; j++) {
                float4 f0 = srcA[2 * j], f1 = srcA[2 * j + 1];
                uint32_t h0, h1, h2, h3, l0, l1, l2, l3;
                split2(f0.x, f0.y, h0, l0); split2(f0.z, f0.w, h1, l1);
                split2(f1.x, f1.y, h2, l2); split2(f1.z, f1.w, h3, l3);
                sts128(sAh + dA + j * 16, h0, h1, h2, h3);
                sts128(sAl + dA + j * 16, l0, l1, l2, l3);
            }
#pragma unroll
            for (int j = 0; j < 8; j++) {
                float4 f0 = srcB[2 * j], f1 = srcB[2 * j + 1];
                uint32_t h0, h1, h2, h3, l0, l1, l2, l3;
                split2(f0.x, f0.y, h0, l0); split2(f0.z, f0.w, h1, l1);
                split2(f1.x, f1.y, h2, l2); split2(f1.z, f1.w, h3, l3);
                sts128(sBh + dA + j * 16, h0, h1, h2, h3);
                sts128(sBl + dA + j * 16, l0, l1, l2, l3);
            }
        }
        __syncthreads();

#pragma unroll
        for (int ks = 0; ks < 4; ks++) {
            const uint32_t colp = (uint32_t)(ks * 16 + (lane >> 4) * 8) * 2;
            const uint32_t aoff = a_rowoff + colp;
            const uint32_t boff = b_rowoff + colp;

            uint32_t a_hi[4][4], a_lo[4][4], b[8][2];
#pragma unroll
            for (int i = 0; i < 4; i++) ldm_x4(a_hi[i], sAh + aoff + i * AM_STEP);
#pragma unroll
            for (int i = 0; i < 4; i++) ldm_x4(a_lo[i], sAl + aoff + i * AM_STEP);
#pragma unroll
            for (int bp = 0; bp < 4; bp++) {
                uint32_t r[4];
                ldm_x4(r, sBh + boff + bp * AM_STEP);
                b[2*bp][0] = r[0]; b[2*bp+1][0] = r[1];
                b[2*bp][1] = r[2]; b[2*bp+1][1] = r[3];
            }
#pragma unroll
            for (int am = 0; am < 4; am++)
#pragma unroll
                for (int bn = 0; bn < 8; bn++) mma16816(acc[am][bn], a_hi[am], b[bn]);
#pragma unroll
            for (int am = 0; am < 4; am++)
#pragma unroll
                for (int bn = 0; bn < 8; bn++) mma16816(acc[am][bn], a_lo[am], b[bn]);
#pragma unroll
            for (int bp = 0; bp < 4; bp++) {
                uint32_t r[4];
                ldm_x4(r, sBl + boff + bp * AM_STEP);
                b[2*bp][0] = r[0]; b[2*bp+1][0] = r[1];
                b[2*bp][1] = r[2]; b[2*bp+1][1] = r[3];
            }
#pragma unroll
            for (int am = 0; am < 4; am++)
#pragma unroll
                for (int bn = 0; bn < 8; bn++) mma16816(acc[am][bn], a_hi[am], b[bn]);
        }
    }

    const int orow  = m0 + wm * 64 + (lane >> 2);
    const int ocol0 = n0 + wn * 64 + (lane & 3) * 2;
#pragma unroll
    for (int am = 0; am < 4; am++) {
#pragma unroll
        for (int bn = 0; bn < 8; bn++) {
            const int col = ocol0 + bn * 8;
            float2 bv = *(const float2*)(bias + col);
            float2 v0, v1;
            v0.x = acc[am][bn][0] + bv.x; v0.y = acc[am][bn][1] + bv.y;
            v1.x = acc[am][bn][2] + bv.x; v1.y = acc[am][bn][3] + bv.y;
            *(float2*)(Y + (size_t)(orow + am * 16)     * 256 + col) = v0;
            *(float2*)(Y + (size_t)(orow + am * 16 + 8) * 256 + col) = v1;
        }
    }
}

// ---------------------------------------------------------------------------
// Fused attention. blockIdx.x < B -> ads side, else cat side. 256 threads.
// smem: 2 x 16 x 260 floats = 33,280 B.
// ---------------------------------------------------------------------------
__device__ __forceinline__ float dot8(float4 a0, float4 b0, float4 a1, float4 b1) {
    return a0.x*b0.x + a0.y*b0.y + a0.z*b0.z + a0.w*b0.w
         + a1.x*b1.x + a1.y*b1.y + a1.z*b1.z + a1.w*b1.w;
}

__device__ void ads_part(float* sm, int b,
                         const float* __restrict__ q, const float* __restrict__ k,
                         const float* __restrict__ v, const float* __restrict__ h,
                         float* __restrict__ out)
{
    float* Qs = sm;              // 16 x 260
    float* Ps = sm + 16 * 260;   // 16 x 260
    const int tid = threadIdx.x;
    const float scale = 0.0625f;

    // load Q (16 x 256)
    {
        const float4* src = (const float4*)(q + (size_t)b * (NA * D));
#pragma unroll
        for (int h2 = 0; h2 < 4; h2++) {
            int i = tid + h2 * 256;
            int row = i >> 6, col = (i & 63) << 2;
            float4 vv = src[i];
            float* d = Qs + row * 260 + col;
            d[0] = vv.x; d[1] = vv.y; d[2] = vv.z; d[3] = vv.w;
        }
    }
    __syncthreads();

    const int w = tid >> 5, l = tid & 31;

    // scores: warp handles 4 keys per batch, K straight from global (coalesced)
#pragma unroll 1
    for (int bat = 0; bat < 8; bat++) {
        const int c0 = w * 32 + bat * 4;
        float4 kA[4], kB[4];
#pragma unroll
        for (int kk = 0; kk < 4; kk++) {
            const float* kr = k + ((size_t)b * NC + c0 + kk) * D;
            kA[kk] = *(const float4*)(kr + 4 * l);
            kB[kk] = *(const float4*)(kr + 128 + 4 * l);
        }
        float s[64];
#pragma unroll
        for (int i = 0; i < 64; i++) s[i] = 0.f;
#pragma unroll
        for (int j = 0; j < 16; j++) {
            float4 qA = *(const float4*)(Qs + j * 260 + 4 * l);
            float4 qB = *(const float4*)(Qs + j * 260 + 128 + 4 * l);
#pragma unroll
            for (int kk = 0; kk < 4; kk++)
                s[kk * 16 + j] += dot8(qA, kA[kk], qB, kB[kk]);
        }
#pragma unroll
        for (int off = 16; off > 0; off >>= 1)
#pragma unroll
            for (int i = 0; i < 64; i++)
                s[i] += __shfl_xor_sync(0xffffffffu, s[i], off);
        if (l < 16) {
#pragma unroll
            for (int kk = 0; kk < 4; kk++)
                Ps[l * 260 + c0 + kk] = s[kk * 16 + l] * scale;
        }
    }
    __syncthreads();

    // softmax over 256 keys, warp per row
    {
        for (int r = w; r < 16; r += 8) {
            float* row = Ps + r * 260;
            float vals[8];
            float mx = -1e30f;
#pragma unroll
            for (int j = 0; j < 8; j++) { vals[j] = row[l + 32*j]; mx = fmaxf(mx, vals[j]); }
#pragma unroll
            for (int o = 16; o > 0; o >>= 1) mx = fmaxf(mx, __shfl_xor_sync(0xffffffffu, mx, o));
            float sum = 0.f;
#pragma unroll
            for (int j = 0; j < 8; j++) { vals[j] = __expf(vals[j] - mx); sum += vals[j]; }
#pragma unroll
            for (int o = 16; o > 0; o >>= 1) sum += __shfl_xor_sync(0xffffffffu, sum, o);
            float inv = 1.f / sum;
#pragma unroll
            for (int j = 0; j < 8; j++) row[l + 32*j] = vals[j] * inv;
        }
    }
    __syncthreads();

    // U = P @ V: thread = (query quad aq, dim group dg)
    const int aq = tid >> 6;      // 0..3 -> queries aq*4..aq*4+3
    const int dg = tid & 63;      // dims dg*4..dg*4+3
    float4 u[4];
#pragma unroll
    for (int qi = 0; qi < 4; qi++) u[qi] = make_float4(0,0,0,0);
    const float* vbase = v + (size_t)b * NC * D + dg * 4;
    const float* prow0 = Ps + (aq * 4) * 260;
#pragma unroll 4
    for (int c = 0; c < 256; c++) {
        float4 vv = *(const float4*)(vbase + (size_t)c * D);
#pragma unroll
        for (int qi = 0; qi < 4; qi++) {
            float p = prow0[qi * 260 + c];
            u[qi].x += p * vv.x; u[qi].y += p * vv.y;
            u[qi].z += p * vv.z; u[qi].w += p * vv.w;
        }
    }

    // residual + l2 norm
    float ssq[4];
#pragma unroll
    for (int qi = 0; qi < 4; qi++) {
        const float4 hv = *(const float4*)(h + ((size_t)b * NA + aq * 4 + qi) * D + dg * 4);
        u[qi].x += hv.x; u[qi].y += hv.y; u[qi].z += hv.z; u[qi].w += hv.w;
        ssq[qi] = u[qi].x*u[qi].x + u[qi].y*u[qi].y + u[qi].z*u[qi].z + u[qi].w*u[qi].w;
    }
#pragma unroll
    for (int off = 16; off > 0; off >>= 1)
#pragma unroll
        for (int qi = 0; qi < 4; qi++)
            ssq[qi] += __shfl_xor_sync(0xffffffffu, ssq[qi], off);
    // combine the two warps of this query quad via smem (reuse Qs)
    if (l == 0) {
#pragma unroll
        for (int qi = 0; qi < 4; qi++) Qs[w * 4 + qi] = ssq[qi];
    }
    __syncthreads();
#pragma unroll
    for (int qi = 0; qi < 4; qi++) {
        float tot = Qs[(2 * aq) * 4 + qi] + Qs[(2 * aq + 1) * 4 + qi];
        float inv = 1.f / fmaxf(sqrtf(tot), 1e-12f);
        float4 o;
        o.x = u[qi].x * inv; o.y = u[qi].y * inv;
        o.z = u[qi].z * inv; o.w = u[qi].w * inv;
        *(float4*)(out + ((size_t)b * NA + aq * 4 + qi) * D + dg * 4) = o;
    }
}

__device__ void cat_part(float* sm, int idx,
                         const float* __restrict__ q, const float* __restrict__ k,
                         const float* __restrict__ v, const float* __restrict__ h,
                         float* __restrict__ out)
{
    float* Ks = sm;              // 16 x 260
    float* Vs = sm + 16 * 260;   // 16 x 260
    const int tid = threadIdx.x;
    const int b = idx >> 3, xp = idx & 7;
    const float scale = 0.0625f;

    {
        const float4* ks = (const float4*)(k + (size_t)b * (NA * D));
        const float4* vs = (const float4*)(v + (size_t)b * (NA * D));
#pragma unroll
        for (int h2 = 0; h2 < 4; h2++) {
            int i = tid + h2 * 256;
            int row = i >> 6, col = (i & 63) << 2;
            float4 kv = ks[i];
            float* dk = Ks + row * 260 + col;
            dk[0] = kv.x; dk[1] = kv.y; dk[2] = kv.z; dk[3] = kv.w;
            float4 vv = vs[i];
            float* dv = Vs + row * 260 + col;
            dv[0] = vv.x; dv[1] = vv.y; dv[2] = vv.z; dv[3] = vv.w;
        }
    }
    __syncthreads();

    const int w = tid >> 5, l = tid & 31;
    const int c0 = xp * 32 + w * 4;
    const size_t gr0 = (size_t)b * NC + c0;

    // 4 queries per warp, dims 4l..4l+3 & 128+4l..+3 per lane
    float4 qA[4], qB[4];
#pragma unroll
    for (int qi = 0; qi < 4; qi++) {
        const float* qr = q + (gr0 + qi) * D;
        qA[qi] = *(const float4*)(qr + 4 * l);
        qB[qi] = *(const float4*)(qr + 128 + 4 * l);
    }

    float s[64];
#pragma unroll
    for (int i = 0; i < 64; i++) s[i] = 0.f;
#pragma unroll
    for (int j = 0; j < 16; j++) {
        float4 kA = *(const float4*)(Ks + j * 260 + 4 * l);
        float4 kB = *(const float4*)(Ks + j * 260 + 128 + 4 * l);
#pragma unroll
        for (int qi = 0; qi < 4; qi++)
            s[qi * 16 + j] += dot8(qA[qi], kA, qB[qi], kB);
    }
#pragma unroll
    for (int off = 16; off > 0; off >>= 1)
#pragma unroll
        for (int i = 0; i < 64; i++)
            s[i] += __shfl_xor_sync(0xffffffffu, s[i], off);

    // softmax per query, in-register (all lanes redundantly)
#pragma unroll
    for (int qi = 0; qi < 4; qi++) {
        float mx = -1e30f;
#pragma unroll
        for (int j = 0; j < 16; j++) mx = fmaxf(mx, s[qi * 16 + j]);
        float sum = 0.f;
#pragma unroll
        for (int j = 0; j < 16; j++) {
            float e = __expf((s[qi * 16 + j] - mx) * scale);
            s[qi * 16 + j] = e; sum += e;
        }
        float inv = 1.f / sum;
#pragma unroll
        for (int j = 0; j < 16; j++) s[qi * 16 + j] *= inv;
    }

    float4 uA[4], uB[4];
#pragma unroll
    for (int qi = 0; qi < 4; qi++) { uA[qi] = make_float4(0,0,0,0); uB[qi] = uA[qi]; }
#pragma unroll
    for (int j = 0; j < 16; j++) {
        float4 vA = *(const float4*)(Vs + j * 260 + 4 * l);
        float4 vB = *(const float4*)(Vs + j * 260 + 128 + 4 * l);
#pragma unroll
        for (int qi = 0; qi < 4; qi++) {
            float p = s[qi * 16 + j];
            uA[qi].x += p * vA.x; uA[qi].y += p * vA.y;
            uA[qi].z += p * vA.z; uA[qi].w += p * vA.w;
            uB[qi].x += p * vB.x; uB[qi].y += p * vB.y;
            uB[qi].z += p * vB.z; uB[qi].w += p * vB.w;
        }
    }

#pragma unroll
    for (int qi = 0; qi < 4; qi++) {
        const float* hr = h + (gr0 + qi) * D;
        float4 rA = *(const float4*)(hr + 4 * l);
        float4 rB = *(const float4*)(hr + 128 + 4 * l);
        rA.x += uA[qi].x; rA.y += uA[qi].y; rA.z += uA[qi].z; rA.w += uA[qi].w;
        rB.x += uB[qi].x; rB.y += uB[qi].y; rB.z += uB[qi].z; rB.w += uB[qi].w;
        float nn = rA.x*rA.x + rA.y*rA.y + rA.z*rA.z + rA.w*rA.w
                 + rB.x*rB.x + rB.y*rB.y + rB.z*rB.z + rB.w*rB.w;
#pragma unroll
        for (int o = 16; o > 0; o >>= 1) nn += __shfl_xor_sync(0xffffffffu, nn, o);
        float inv = 1.f / fmaxf(sqrtf(nn), 1e-12f);
        float* orow = out + (gr0 + qi) * D;
        *(float4*)(orow + 4 * l) =
            make_float4(rA.x*inv, rA.y*inv, rA.z*inv, rA.w*inv);
        *(float4*)(orow + 128 + 4 * l) =
            make_float4(rB.x*inv, rB.y*inv, rB.z*inv, rB.w*inv);
    }
}

__global__ void __launch_bounds__(256)
attn_fused(const float* qa, const float* kc, const float* vc, const float* hA,
           const float* qc, const float* ka, const float* va, const float* hC,
           float* outA, float* outC, int B)
{
    extern __shared__ __align__(16) float sm[];
    if ((int)blockIdx.x < B)
        ads_part(sm, blockIdx.x, qa, kc, vc, hA, outA);
    else
        cat_part(sm, blockIdx.x - B, qc, ka, va, hC, outC);
}

// ---------------------------------------------------------------------------
// Launch
// ---------------------------------------------------------------------------
extern "C" void kernel_launch(void* const* d_in, const int* in_sizes, int n_in,
                              void* d_out, int out_size)
{
    const float* h_ads = (const float*)d_in[0];
    const float* h_cat = (const float*)d_in[1];
    const float* Wq_a = (const float*)d_in[2];  const float* bq_a = (const float*)d_in[3];
    const float* Wk_a = (const float*)d_in[4];  const float* bk_a = (const float*)d_in[5];
    const float* Wv_a = (const float*)d_in[6];  const float* bv_a = (const float*)d_in[7];
    const float* Wq_c = (const float*)d_in[8];  const float* bq_c = (const float*)d_in[9];
    const float* Wk_c = (const float*)d_in[10]; const float* bk_c = (const float*)d_in[11];
    const float* Wv_c = (const float*)d_in[12]; const float* bv_c = (const float*)d_in[13];

    const int M_ads = in_sizes[0] / D;   // 8192
    const int M_cat = in_sizes[1] / D;   // 131072
    const int B     = M_ads / NA;        // 512

    float *qa, *ka, *va, *qc, *kc, *vc;
    cudaGetSymbolAddress((void**)&qa, g_qads);
    cudaGetSymbolAddress((void**)&ka, g_kads);
    cudaGetSymbolAddress((void**)&va, g_vads);
    cudaGetSymbolAddress((void**)&qc, g_qcat);
    cudaGetSymbolAddress((void**)&kc, g_kcat);
    cudaGetSymbolAddress((void**)&vc, g_vcat);

    const int gemm_smem = 4 * 128 * LDT * 2;   // 73,728 B
    cudaFuncSetAttribute((const void*)gemm_mma3,
                         cudaFuncAttributeMaxDynamicSharedMemorySize, gemm_smem);

    gemm_mma3<<<dim3(M_ads / 128, 2, 3), 128, gemm_smem>>>(
        h_ads, Wq_a, Wk_a, Wv_a, bq_a, bk_a, bv_a, qa, ka, va);
    gemm_mma3<<<dim3(M_cat / 128, 2, 3), 128, gemm_smem>>>(
        h_cat, Wq_c, Wk_c, Wv_c, bq_c, bk_c, bv_c, qc, kc, vc);

    const int attn_smem = 2 * 16 * 260 * 4;    // 33,280 B
    cudaFuncSetAttribute((const void*)attn_fused,
                         cudaFuncAttributeMaxDynamicSharedMemorySize, attn_smem);

    attn_fused<<<B + 8 * B, 256, attn_smem>>>(
        qa, kc, vc, h_ads, qc, ka, va, h_cat,
        (float*)d_out, (float*)d_out + (size_t)M_ads * D, B);
}

// round 6
// speedup vs baseline: 1.4759x; 1.2462x over previous
#include <cuda_runtime.h>
#include <cuda_bf16.h>
#include <math.h>
#include <stdint.h>

#define D   256
#define NA  16
#define NC  256

// ---------------------------------------------------------------------------
// Scratch (device globals — no allocation allowed in kernel_launch)
// ---------------------------------------------------------------------------
__device__ float g_qads[8192u  * 256u];
__device__ float g_kads[8192u  * 256u];
__device__ float g_vads[8192u  * 256u];
__device__ float g_qcat[131072u * 256u];
__device__ float g_kcat[131072u * 256u];
__device__ float g_vcat[131072u * 256u];
__device__ __nv_bfloat16 gx_ads_hi[8192u  * 256u];
__device__ __nv_bfloat16 gx_ads_lo[8192u  * 256u];
__device__ __nv_bfloat16 gx_cat_hi[131072u * 256u];
__device__ __nv_bfloat16 gx_cat_lo[131072u * 256u];
__device__ __nv_bfloat16 gw_hi[6u * 65536u];
__device__ __nv_bfloat16 gw_lo[6u * 65536u];

// ---------------------------------------------------------------------------
// PTX helpers (arch-neutral sm_80+ — harness ptxas target is plain sm_103)
// ---------------------------------------------------------------------------
__device__ __forceinline__ uint32_t smem_u32(const void* p) {
    uint32_t a;
    asm("{ .reg .u64 t; cvta.to.shared.u64 t, %1; cvt.u32.u64 %0, t; }"
        : "=r"(a) : "l"(p));
    return a;
}
__device__ __forceinline__ void cpa16(uint32_t dst, const void* src) {
    asm volatile("cp.async.ca.shared.global [%0], [%1], 16;"
                 :: "r"(dst), "l"(src) : "memory");
}
__device__ __forceinline__ void ldm_x4(uint32_t* r, uint32_t addr) {
    asm volatile("ldmatrix.sync.aligned.m8n8.x4.shared.b16 {%0,%1,%2,%3}, [%4];"
                 : "=r"(r[0]), "=r"(r[1]), "=r"(r[2]), "=r"(r[3]) : "r"(addr));
}
__device__ __forceinline__ void mma16816(float* c, const uint32_t* a,
                                         const uint32_t* b) {
    asm volatile(
        "mma.sync.aligned.m16n8k16.row.col.f32.bf16.bf16.f32 "
        "{%0,%1,%2,%3}, {%4,%5,%6,%7}, {%8,%9}, {%0,%1,%2,%3};"
        : "+f"(c[0]), "+f"(c[1]), "+f"(c[2]), "+f"(c[3])
        : "r"(a[0]), "r"(a[1]), "r"(a[2]), "r"(a[3]), "r"(b[0]), "r"(b[1]));
}
__device__ __forceinline__ void split2(float a, float b, uint32_t& hp, uint32_t& lp) {
    asm("cvt.rn.bf16x2.f32 %0, %1, %2;" : "=r"(hp) : "f"(b), "f"(a));
    float af = __uint_as_float(hp << 16);
    float bf = __uint_as_float(hp & 0xFFFF0000u);
    float la = a - af, lb = b - bf;
    asm("cvt.rn.bf16x2.f32 %0, %1, %2;" : "=r"(lp) : "f"(lb), "f"(la));
}

// ---------------------------------------------------------------------------
// Conversion prepass: fp32 -> packed bf16 hi/lo
// ---------------------------------------------------------------------------
__global__ void __launch_bounds__(256)
conv_x(const float4* __restrict__ src, uint2* __restrict__ hi,
       uint2* __restrict__ lo, int n4)
{
    for (int i = blockIdx.x * blockDim.x + threadIdx.x; i < n4;
         i += gridDim.x * blockDim.x) {
        float4 f = src[i];
        uint32_t h0, h1, l0, l1;
        split2(f.x, f.y, h0, l0);
        split2(f.z, f.w, h1, l1);
        hi[i] = make_uint2(h0, h1);
        lo[i] = make_uint2(l0, l1);
    }
}

__global__ void __launch_bounds__(256)
conv_w(const float* w0, const float* w1, const float* w2,
       const float* w3, const float* w4, const float* w5,
       uint2* __restrict__ hi, uint2* __restrict__ lo)
{
    const int z = blockIdx.y;
    const float* W = (z == 0) ? w0 : (z == 1) ? w1 : (z == 2) ? w2
                   : (z == 3) ? w3 : (z == 4) ? w4 : w5;
    const int i = blockIdx.x * 256 + threadIdx.x;   // 0..16383
    float4 f = ((const float4*)W)[i];
    uint32_t h0, h1, l0, l1;
    split2(f.x, f.y, h0, l0);
    split2(f.z, f.w, h1, l1);
    hi[z * 16384 + i] = make_uint2(h0, h1);
    lo[z * 16384 + i] = make_uint2(l0, l1);
}

// ---------------------------------------------------------------------------
// Pipelined bf16 GEMM: Y[M,256] = X @ W^T + bias (W z-fused: q/k/v)
// 256 thr / 8 warps (4m x 2n of 32x64), CTA tile 128x128, BK=32,
// cp.async double-buffered, 3-term split from preconverted hi/lo.
// smem per stage: 4 matrices x 128 rows x 80B = 40,960 B; 2 stages = 81,920 B.
// ---------------------------------------------------------------------------
#define SROW   80u      // bytes per smem row (32 bf16 = 64B data + 16B pad)
#define SMAT   10240u   // one matrix (128 rows)
#define SSTAGE 40960u   // one stage (Ahi|Alo|Bhi|Blo)

__global__ void __launch_bounds__(256, 2)
gemm_pipe(const __nv_bfloat16* __restrict__ Xhi, const __nv_bfloat16* __restrict__ Xlo,
          const __nv_bfloat16* __restrict__ Wh_all, const __nv_bfloat16* __restrict__ Wl_all,
          const float* __restrict__ b0, const float* __restrict__ b1,
          const float* __restrict__ b2,
          float* __restrict__ Y0, float* __restrict__ Y1, float* __restrict__ Y2)
{
    const int z = blockIdx.z;
    const __nv_bfloat16* Whi = Wh_all + (size_t)z * 65536;
    const __nv_bfloat16* Wlo = Wl_all + (size_t)z * 65536;
    const float* bias = (z == 0) ? b0 : (z == 1) ? b1 : b2;
    float*       Y    = (z == 0) ? Y0 : (z == 1) ? Y1 : Y2;

    extern __shared__ __align__(16) char smraw[];
    const uint32_t sb = smem_u32(smraw);

    const int tid  = threadIdx.x;
    const int lane = tid & 31;
    const int wid  = tid >> 5;
    const int wm   = wid & 3;
    const int wn   = wid >> 2;
    const int m0   = blockIdx.x * 128;
    const int n0   = blockIdx.y * 128;

    float acc[2][8][4];
#pragma unroll
    for (int i = 0; i < 2; i++)
#pragma unroll
        for (int j = 0; j < 8; j++)
#pragma unroll
            for (int t = 0; t < 4; t++) acc[i][j][t] = 0.f;

    // per-thread copy coordinates: 512 16B-copies per matrix, 2 per thread
    // c?s is a BYTE offset within the 64B row chunk (0,16,32,48)
    const int c0r = tid >> 2,           c0s = (tid & 3) * 16;
    const int c1r = (tid + 256) >> 2,   c1s = ((tid + 256) & 3) * 16;

#define ISSUE(stage, kk)                                                          \
    do {                                                                          \
        const uint32_t s = sb + (stage) * SSTAGE;                                 \
        const char* xh = (const char*)(Xhi + (size_t)(m0 + c0r) * 256 + (kk));    \
        const char* xl = (const char*)(Xlo + (size_t)(m0 + c0r) * 256 + (kk));    \
        const char* wh = (const char*)(Whi + (size_t)(n0 + c0r) * 256 + (kk));    \
        const char* wl = (const char*)(Wlo + (size_t)(n0 + c0r) * 256 + (kk));    \
        cpa16(s + 0*SMAT + c0r * SROW + c0s, xh + c0s);                           \
        cpa16(s + 1*SMAT + c0r * SROW + c0s, xl + c0s);                           \
        cpa16(s + 2*SMAT + c0r * SROW + c0s, wh + c0s);                           \
        cpa16(s + 3*SMAT + c0r * SROW + c0s, wl + c0s);                           \
        const char* xh2 = (const char*)(Xhi + (size_t)(m0 + c1r) * 256 + (kk));   \
        const char* xl2 = (const char*)(Xlo + (size_t)(m0 + c1r) * 256 + (kk));   \
        const char* wh2 = (const char*)(Whi + (size_t)(n0 + c1r) * 256 + (kk));   \
        const char* wl2 = (const char*)(Wlo + (size_t)(n0 + c1r) * 256 + (kk));   \
        cpa16(s + 0*SMAT + c1r * SROW + c1s, xh2 + c1s);                          \
        cpa16(s + 1*SMAT + c1r * SROW + c1s, xl2 + c1s);                          \
        cpa16(s + 2*SMAT + c1r * SROW + c1s, wh2 + c1s);                          \
        cpa16(s + 3*SMAT + c1r * SROW + c1s, wl2 + c1s);                          \
        asm volatile("cp.async.commit_group;" ::: "memory");                      \
    } while (0)

    const uint32_t a_row = (uint32_t)(wm * 32 + (lane & 15)) * SROW;
    const uint32_t b_row = (uint32_t)(wn * 64 + (lane & 15)) * SROW;
    const uint32_t STEP16 = 16u * SROW;

    ISSUE(0, 0);

#pragma unroll 1
    for (int c = 0; c < 8; c++) {
        if (c < 7) {
            ISSUE((c + 1) & 1, (c + 1) * 32);
            asm volatile("cp.async.wait_group 1;" ::: "memory");
        } else {
            asm volatile("cp.async.wait_group 0;" ::: "memory");
        }
        __syncthreads();

        const uint32_t st = sb + (uint32_t)(c & 1) * SSTAGE;
#pragma unroll
        for (int ks = 0; ks < 2; ks++) {
            const uint32_t colp = (uint32_t)(ks * 32 + (lane >> 4) * 16);
            uint32_t ah[2][4], al[2][4], b[8][2], r[4];

            ldm_x4(ah[0], st + 0*SMAT + a_row + colp);
            ldm_x4(ah[1], st + 0*SMAT + a_row + STEP16 + colp);
#pragma unroll
            for (int bp = 0; bp < 4; bp++) {
                ldm_x4(r, st + 2*SMAT + b_row + bp * STEP16 + colp);
                b[2*bp][0] = r[0]; b[2*bp+1][0] = r[1];
                b[2*bp][1] = r[2]; b[2*bp+1][1] = r[3];
            }
#pragma unroll
            for (int am = 0; am < 2; am++)
#pragma unroll
                for (int bn = 0; bn < 8; bn++) mma16816(acc[am][bn], ah[am], b[bn]);

            ldm_x4(al[0], st + 1*SMAT + a_row + colp);
            ldm_x4(al[1], st + 1*SMAT + a_row + STEP16 + colp);
#pragma unroll
            for (int am = 0; am < 2; am++)
#pragma unroll
                for (int bn = 0; bn < 8; bn++) mma16816(acc[am][bn], al[am], b[bn]);

#pragma unroll
            for (int bp = 0; bp < 4; bp++) {
                ldm_x4(r, st + 3*SMAT + b_row + bp * STEP16 + colp);
                b[2*bp][0] = r[0]; b[2*bp+1][0] = r[1];
                b[2*bp][1] = r[2]; b[2*bp+1][1] = r[3];
            }
#pragma unroll
            for (int am = 0; am < 2; am++)
#pragma unroll
                for (int bn = 0; bn < 8; bn++) mma16816(acc[am][bn], ah[am], b[bn]);
        }
        __syncthreads();
    }

    const int orow  = m0 + wm * 32 + (lane >> 2);
    const int ocol0 = n0 + wn * 64 + (lane & 3) * 2;
#pragma unroll
    for (int am = 0; am < 2; am++) {
#pragma unroll
        for (int bn = 0; bn < 8; bn++) {
            const int col = ocol0 + bn * 8;
            float2 bv = *(const float2*)(bias + col);
            float2 v0, v1;
            v0.x = acc[am][bn][0] + bv.x; v0.y = acc[am][bn][1] + bv.y;
            v1.x = acc[am][bn][2] + bv.x; v1.y = acc[am][bn][3] + bv.y;
            *(float2*)(Y + (size_t)(orow + am * 16)     * 256 + col) = v0;
            *(float2*)(Y + (size_t)(orow + am * 16 + 8) * 256 + col) = v1;
        }
    }
}

// ---------------------------------------------------------------------------
// Fused attention. blockIdx.x < B -> ads, else cat. 256 threads.
// ---------------------------------------------------------------------------
__device__ __forceinline__ float dot8(float4 a0, float4 b0, float4 a1, float4 b1) {
    return a0.x*b0.x + a0.y*b0.y + a0.z*b0.z + a0.w*b0.w
         + a1.x*b1.x + a1.y*b1.y + a1.z*b1.z + a1.w*b1.w;
}

__device__ void ads_part(float* sm, int b,
                         const float* __restrict__ q, const float* __restrict__ k,
                         const float* __restrict__ v, const float* __restrict__ h,
                         float* __restrict__ out)
{
    float* Qs = sm;
    float* Ps = sm + 16 * 260;
    const int tid = threadIdx.x;
    const float scale = 0.0625f;

    {
        const float4* src = (const float4*)(q + (size_t)b * (NA * D));
#pragma unroll
        for (int h2 = 0; h2 < 4; h2++) {
            int i = tid + h2 * 256;
            int row = i >> 6, col = (i & 63) << 2;
            float4 vv = src[i];
            float* d = Qs + row * 260 + col;
            d[0] = vv.x; d[1] = vv.y; d[2] = vv.z; d[3] = vv.w;
        }
    }
    __syncthreads();

    const int w = tid >> 5, l = tid & 31;

#pragma unroll 1
    for (int bat = 0; bat < 8; bat++) {
        const int c0 = w * 32 + bat * 4;
        float4 kA[4], kB[4];
#pragma unroll
        for (int kk = 0; kk < 4; kk++) {
            const float* kr = k + ((size_t)b * NC + c0 + kk) * D;
            kA[kk] = *(const float4*)(kr + 4 * l);
            kB[kk] = *(const float4*)(kr + 128 + 4 * l);
        }
        float s[64];
#pragma unroll
        for (int i = 0; i < 64; i++) s[i] = 0.f;
#pragma unroll
        for (int j = 0; j < 16; j++) {
            float4 qA = *(const float4*)(Qs + j * 260 + 4 * l);
            float4 qB = *(const float4*)(Qs + j * 260 + 128 + 4 * l);
#pragma unroll
            for (int kk = 0; kk < 4; kk++)
                s[kk * 16 + j] += dot8(qA, kA[kk], qB, kB[kk]);
        }
#pragma unroll
        for (int off = 16; off > 0; off >>= 1)
#pragma unroll
            for (int i = 0; i < 64; i++)
                s[i] += __shfl_xor_sync(0xffffffffu, s[i], off);
        if (l < 16) {
#pragma unroll
            for (int kk = 0; kk < 4; kk++)
                Ps[l * 260 + c0 + kk] = s[kk * 16 + l] * scale;
        }
    }
    __syncthreads();

    {
        for (int r = w; r < 16; r += 8) {
            float* row = Ps + r * 260;
            float vals[8];
            float mx = -1e30f;
#pragma unroll
            for (int j = 0; j < 8; j++) { vals[j] = row[l + 32*j]; mx = fmaxf(mx, vals[j]); }
#pragma unroll
            for (int o = 16; o > 0; o >>= 1) mx = fmaxf(mx, __shfl_xor_sync(0xffffffffu, mx, o));
            float sum = 0.f;
#pragma unroll
            for (int j = 0; j < 8; j++) { vals[j] = __expf(vals[j] - mx); sum += vals[j]; }
#pragma unroll
            for (int o = 16; o > 0; o >>= 1) sum += __shfl_xor_sync(0xffffffffu, sum, o);
            float inv = 1.f / sum;
#pragma unroll
            for (int j = 0; j < 8; j++) row[l + 32*j] = vals[j] * inv;
        }
    }
    __syncthreads();

    const int aq = tid >> 6;
    const int dg = tid & 63;
    float4 u[4];
#pragma unroll
    for (int qi = 0; qi < 4; qi++) u[qi] = make_float4(0,0,0,0);
    const float* vbase = v + (size_t)b * NC * D + dg * 4;
    const float* prow0 = Ps + (aq * 4) * 260;
#pragma unroll 4
    for (int c = 0; c < 256; c++) {
        float4 vv = *(const float4*)(vbase + (size_t)c * D);
#pragma unroll
        for (int qi = 0; qi < 4; qi++) {
            float p = prow0[qi * 260 + c];
            u[qi].x += p * vv.x; u[qi].y += p * vv.y;
            u[qi].z += p * vv.z; u[qi].w += p * vv.w;
        }
    }

    float ssq[4];
#pragma unroll
    for (int qi = 0; qi < 4; qi++) {
        const float4 hv = *(const float4*)(h + ((size_t)b * NA + aq * 4 + qi) * D + dg * 4);
        u[qi].x += hv.x; u[qi].y += hv.y; u[qi].z += hv.z; u[qi].w += hv.w;
        ssq[qi] = u[qi].x*u[qi].x + u[qi].y*u[qi].y + u[qi].z*u[qi].z + u[qi].w*u[qi].w;
    }
#pragma unroll
    for (int off = 16; off > 0; off >>= 1)
#pragma unroll
        for (int qi = 0; qi < 4; qi++)
            ssq[qi] += __shfl_xor_sync(0xffffffffu, ssq[qi], off);
    if (l == 0) {
#pragma unroll
        for (int qi = 0; qi < 4; qi++) Qs[w * 4 + qi] = ssq[qi];
    }
    __syncthreads();
#pragma unroll
    for (int qi = 0; qi < 4; qi++) {
        float tot = Qs[(2 * aq) * 4 + qi] + Qs[(2 * aq + 1) * 4 + qi];
        float inv = 1.f / fmaxf(sqrtf(tot), 1e-12f);
        float4 o;
        o.x = u[qi].x * inv; o.y = u[qi].y * inv;
        o.z = u[qi].z * inv; o.w = u[qi].w * inv;
        *(float4*)(out + ((size_t)b * NA + aq * 4 + qi) * D + dg * 4) = o;
    }
}

__device__ void cat_part(float* sm, int idx,
                         const float* __restrict__ q, const float* __restrict__ k,
                         const float* __restrict__ v, const float* __restrict__ h,
                         float* __restrict__ out)
{
    float* Ks = sm;
    float* Vs = sm + 16 * 260;
    const int tid = threadIdx.x;
    const int b = idx >> 3, xp = idx & 7;
    const float scale = 0.0625f;

    {
        const float4* ks = (const float4*)(k + (size_t)b * (NA * D));
        const float4* vs = (const float4*)(v + (size_t)b * (NA * D));
#pragma unroll
        for (int h2 = 0; h2 < 4; h2++) {
            int i = tid + h2 * 256;
            int row = i >> 6, col = (i & 63) << 2;
            float4 kv = ks[i];
            float* dk = Ks + row * 260 + col;
            dk[0] = kv.x; dk[1] = kv.y; dk[2] = kv.z; dk[3] = kv.w;
            float4 vv = vs[i];
            float* dv = Vs + row * 260 + col;
            dv[0] = vv.x; dv[1] = vv.y; dv[2] = vv.z; dv[3] = vv.w;
        }
    }
    __syncthreads();

    const int w = tid >> 5, l = tid & 31;
    const int c0 = xp * 32 + w * 4;
    const size_t gr0 = (size_t)b * NC + c0;

    float4 qA[4], qB[4];
#pragma unroll
    for (int qi = 0; qi < 4; qi++) {
        const float* qr = q + (gr0 + qi) * D;
        qA[qi] = *(const float4*)(qr + 4 * l);
        qB[qi] = *(const float4*)(qr + 128 + 4 * l);
    }

    float s[64];
#pragma unroll
    for (int i = 0; i < 64; i++) s[i] = 0.f;
#pragma unroll
    for (int j = 0; j < 16; j++) {
        float4 kA = *(const float4*)(Ks + j * 260 + 4 * l);
        float4 kB = *(const float4*)(Ks + j * 260 + 128 + 4 * l);
#pragma unroll
        for (int qi = 0; qi < 4; qi++)
            s[qi * 16 + j] += dot8(qA[qi], kA, qB[qi], kB);
    }
#pragma unroll
    for (int off = 16; off > 0; off >>= 1)
#pragma unroll
        for (int i = 0; i < 64; i++)
            s[i] += __shfl_xor_sync(0xffffffffu, s[i], off);

#pragma unroll
    for (int qi = 0; qi < 4; qi++) {
        float mx = -1e30f;
#pragma unroll
        for (int j = 0; j < 16; j++) mx = fmaxf(mx, s[qi * 16 + j]);
        float sum = 0.f;
#pragma unroll
        for (int j = 0; j < 16; j++) {
            float e = __expf((s[qi * 16 + j] - mx) * scale);
            s[qi * 16 + j] = e; sum += e;
        }
        float inv = 1.f / sum;
#pragma unroll
        for (int j = 0; j < 16; j++) s[qi * 16 + j] *= inv;
    }

    float4 uA[4], uB[4];
#pragma unroll
    for (int qi = 0; qi < 4; qi++) { uA[qi] = make_float4(0,0,0,0); uB[qi] = uA[qi]; }
#pragma unroll
    for (int j = 0; j < 16; j++) {
        float4 vA = *(const float4*)(Vs + j * 260 + 4 * l);
        float4 vB = *(const float4*)(Vs + j * 260 + 128 + 4 * l);
#pragma unroll
        for (int qi = 0; qi < 4; qi++) {
            float p = s[qi * 16 + j];
            uA[qi].x += p * vA.x; uA[qi].y += p * vA.y;
            uA[qi].z += p * vA.z; uA[qi].w += p * vA.w;
            uB[qi].x += p * vB.x; uB[qi].y += p * vB.y;
            uB[qi].z += p * vB.z; uB[qi].w += p * vB.w;
        }
    }

#pragma unroll
    for (int qi = 0; qi < 4; qi++) {
        const float* hr = h + (gr0 + qi) * D;
        float4 rA = *(const float4*)(hr + 4 * l);
        float4 rB = *(const float4*)(hr + 128 + 4 * l);
        rA.x += uA[qi].x; rA.y += uA[qi].y; rA.z += uA[qi].z; rA.w += uA[qi].w;
        rB.x += uB[qi].x; rB.y += uB[qi].y; rB.z += uB[qi].z; rB.w += uB[qi].w;
        float nn = rA.x*rA.x + rA.y*rA.y + rA.z*rA.z + rA.w*rA.w
                 + rB.x*rB.x + rB.y*rB.y + rB.z*rB.z + rB.w*rB.w;
#pragma unroll
        for (int o = 16; o > 0; o >>= 1) nn += __shfl_xor_sync(0xffffffffu, nn, o);
        float inv = 1.f / fmaxf(sqrtf(nn), 1e-12f);
        float* orow = out + (gr0 + qi) * D;
        *(float4*)(orow + 4 * l) =
            make_float4(rA.x*inv, rA.y*inv, rA.z*inv, rA.w*inv);
        *(float4*)(orow + 128 + 4 * l) =
            make_float4(rB.x*inv, rB.y*inv, rB.z*inv, rB.w*inv);
    }
}

__global__ void __launch_bounds__(256)
attn_fused(const float* qa, const float* kc, const float* vc, const float* hA,
           const float* qc, const float* ka, const float* va, const float* hC,
           float* outA, float* outC, int B)
{
    extern __shared__ __align__(16) float sm[];
    if ((int)blockIdx.x < B)
        ads_part(sm, blockIdx.x, qa, kc, vc, hA, outA);
    else
        cat_part(sm, blockIdx.x - B, qc, ka, va, hC, outC);
}

// ---------------------------------------------------------------------------
// Launch
// ---------------------------------------------------------------------------
extern "C" void kernel_launch(void* const* d_in, const int* in_sizes, int n_in,
                              void* d_out, int out_size)
{
    const float* h_ads = (const float*)d_in[0];
    const float* h_cat = (const float*)d_in[1];
    const float* Wq_a = (const float*)d_in[2];  const float* bq_a = (const float*)d_in[3];
    const float* Wk_a = (const float*)d_in[4];  const float* bk_a = (const float*)d_in[5];
    const float* Wv_a = (const float*)d_in[6];  const float* bv_a = (const float*)d_in[7];
    const float* Wq_c = (const float*)d_in[8];  const float* bq_c = (const float*)d_in[9];
    const float* Wk_c = (const float*)d_in[10]; const float* bk_c = (const float*)d_in[11];
    const float* Wv_c = (const float*)d_in[12]; const float* bv_c = (const float*)d_in[13];

    const int M_ads = in_sizes[0] / D;   // 8192
    const int M_cat = in_sizes[1] / D;   // 131072
    const int B     = M_ads / NA;        // 512

    float *qa, *ka, *va, *qc, *kc, *vc;
    cudaGetSymbolAddress((void**)&qa, g_qads);
    cudaGetSymbolAddress((void**)&ka, g_kads);
    cudaGetSymbolAddress((void**)&va, g_vads);
    cudaGetSymbolAddress((void**)&qc, g_qcat);
    cudaGetSymbolAddress((void**)&kc, g_kcat);
    cudaGetSymbolAddress((void**)&vc, g_vcat);
    __nv_bfloat16 *xah, *xal, *xch, *xcl, *wh, *wl;
    cudaGetSymbolAddress((void**)&xah, gx_ads_hi);
    cudaGetSymbolAddress((void**)&xal, gx_ads_lo);
    cudaGetSymbolAddress((void**)&xch, gx_cat_hi);
    cudaGetSymbolAddress((void**)&xcl, gx_cat_lo);
    cudaGetSymbolAddress((void**)&wh, gw_hi);
    cudaGetSymbolAddress((void**)&wl, gw_lo);

    // conversion prepass
    conv_x<<<512,  256>>>((const float4*)h_ads, (uint2*)xah, (uint2*)xal,
                          M_ads * D / 4);
    conv_x<<<4096, 256>>>((const float4*)h_cat, (uint2*)xch, (uint2*)xcl,
                          M_cat * D / 4);
    conv_w<<<dim3(64, 6), 256>>>(Wq_a, Wk_a, Wv_a, Wq_c, Wk_c, Wv_c,
                                 (uint2*)wh, (uint2*)wl);

    const int gemm_smem = 2 * SSTAGE;   // 81,920 B
    cudaFuncSetAttribute((const void*)gemm_pipe,
                         cudaFuncAttributeMaxDynamicSharedMemorySize, gemm_smem);

    gemm_pipe<<<dim3(M_ads / 128, 2, 3), 256, gemm_smem>>>(
        xah, xal, wh, wl, bq_a, bk_a, bv_a, qa, ka, va);
    gemm_pipe<<<dim3(M_cat / 128, 2, 3), 256, gemm_smem>>>(
        xch, xcl, wh + 3u * 65536u, wl + 3u * 65536u, bq_c, bk_c, bv_c, qc, kc, vc);

    const int attn_smem = 2 * 16 * 260 * 4;
    cudaFuncSetAttribute((const void*)attn_fused,
                         cudaFuncAttributeMaxDynamicSharedMemorySize, attn_smem);

    attn_fused<<<B + 8 * B, 256, attn_smem>>>(
        qa, kc, vc, h_ads, qc, ka, va, h_cat,
        (float*)d_out, (float*)d_out + (size_t)M_ads * D, B);
}